// round 10
// baseline (speedup 1.0000x reference)
#include <cuda_runtime.h>
#include <cstdint>

#define B_ 4
#define N_ 4096
#define K_ 20
#define M_ 12288  // 3*N_

// ---------------- scratch (device globals; no runtime allocation) ----------------
__device__ float g_pool64[B_ * 64 * 3 * N_];
__device__ float g_act256[B_ * 256 * 3 * N_];
__device__ float g_d0[B_ * 256 * 3 * N_];
__device__ float g_net1[B_ * 128 * 3 * N_];
__device__ float g_d1[B_ * 128 * 3 * N_];
__device__ float g_netA[B_ * 128 * 3 * N_];
__device__ float g_netB[B_ * 128 * 3 * N_];
__device__ float g_pooled[B_ * 128 * 3];
__device__ float g_biasA[B_ * 256 * 3];
__device__ float g_biasS[B_ * 128 * 3];
__device__ int   g_knn[B_ * N_ * K_];

__device__ __forceinline__ uint32_t cvt_tf32(float x) {
    uint32_t r;
    asm("cvt.rna.tf32.f32 %0, %1;" : "=r"(r) : "f"(x));
    return r;
}

// ---------------- KNN: brute-force top-20 by neg squared distance ----------------
__global__ void __launch_bounds__(128) knn_kernel(const float* __restrict__ pc,
                                                  int* __restrict__ knn) {
    __shared__ float s_pts[N_ * 3];  // 48KB
    int b = blockIdx.y;
    int tid = threadIdx.x;
    const float* pb = pc + (size_t)b * N_ * 3;
    for (int i = tid; i < N_ * 3; i += 128) s_pts[i] = pb[i];
    __syncthreads();

    int n = blockIdx.x * 128 + tid;
    float qx = s_pts[n * 3 + 0], qy = s_pts[n * 3 + 1], qz = s_pts[n * 3 + 2];
    float sqn = qx * qx + qy * qy + qz * qz;

    float best[K_];
    int bidx[K_];
#pragma unroll
    for (int i = 0; i < K_; i++) { best[i] = -1e30f; bidx[i] = 0; }
    float kmin = -1e30f;

    for (int m = 0; m < N_; m++) {
        float mx = s_pts[m * 3 + 0], my = s_pts[m * 3 + 1], mz = s_pts[m * 3 + 2];
        float inner = qx * mx + qy * my + qz * mz;
        float sqm = mx * mx + my * my + mz * mz;
        float v = 2.0f * inner - sqn - sqm;
        if (v > kmin) {  // strict: ties keep earlier index (matches lax.top_k)
            int j = K_ - 1;
            while (j > 0 && best[j - 1] < v) {
                best[j] = best[j - 1]; bidx[j] = bidx[j - 1]; j--;
            }
            best[j] = v; bidx[j] = m;
            kmin = best[K_ - 1];
        }
    }
    int* o = knn + ((size_t)b * N_ + n) * K_;
#pragma unroll
    for (int i = 0; i < K_; i++) o[i] = bidx[i];
}

// ---------------- edge conv (3->64) + vn_leaky + max-pool over k ----------------
__global__ void __launch_bounds__(128) edge_conv_kernel(
    const float* __restrict__ pc, const int* __restrict__ knn,
    const float* __restrict__ Wf, const float* __restrict__ Wd,
    const float* __restrict__ W2, float* __restrict__ outp) {
    __shared__ float s_net[64 * 60];   // [o][kk][v]
    __shared__ float s_W2T[64 * 65];   // transposed, padded: [c][o]
    __shared__ float s_dot[64 * 20];
    __shared__ float s_e[K_][3], s_cr[K_][3], s_x[3];
    __shared__ float s_Wf[192], s_Wd[192];

    int n = blockIdx.x, b = blockIdx.y;
    int tid = threadIdx.x;  // 128

    for (int i = tid; i < 192; i += 128) { s_Wf[i] = Wf[i]; s_Wd[i] = Wd[i]; }
    for (int i = tid; i < 4096; i += 128) {
        int o = i >> 6, c = i & 63;
        s_W2T[c * 65 + o] = W2[i];
    }
    if (tid < 3) s_x[tid] = pc[((size_t)b * N_ + n) * 3 + tid];
    __syncthreads();

    if (tid < K_) {
        int m = knn[((size_t)b * N_ + n) * K_ + tid];
        const float* pm = pc + ((size_t)b * N_ + m) * 3;
        float nx = pm[0], ny = pm[1], nz = pm[2];
        float x0 = s_x[0], x1 = s_x[1], x2 = s_x[2];
        s_e[tid][0] = nx - x0; s_e[tid][1] = ny - x1; s_e[tid][2] = nz - x2;
        s_cr[tid][0] = ny * x2 - nz * x1;  // cross(nbr, x)
        s_cr[tid][1] = nz * x0 - nx * x2;
        s_cr[tid][2] = nx * x1 - ny * x0;
    }
    __syncthreads();

    for (int t = tid; t < 64 * K_; t += 128) {
        int o = t / K_, kk = t % K_;
        float wf0 = s_Wf[o * 3 + 0], wf1 = s_Wf[o * 3 + 1], wf2 = s_Wf[o * 3 + 2];
        float wd0 = s_Wd[o * 3 + 0], wd1 = s_Wd[o * 3 + 1], wd2 = s_Wd[o * 3 + 2];
        float F[3], D[3];
#pragma unroll
        for (int v = 0; v < 3; v++) {
            float e = s_e[kk][v], xx = s_x[v], cr = s_cr[kk][v];
            F[v] = wf0 * e + wf1 * xx + wf2 * cr;
            D[v] = wd0 * e + wd1 * xx + wd2 * cr;
        }
        float dot = F[0] * D[0] + F[1] * D[1] + F[2] * D[2];
        if (dot < 0.0f) {
            float s = dot / (D[0] * D[0] + D[1] * D[1] + D[2] * D[2] + 1e-6f);
            F[0] -= s * D[0]; F[1] -= s * D[1]; F[2] -= s * D[2];
        }
        s_net[o * 60 + kk * 3 + 0] = F[0];
        s_net[o * 60 + kk * 3 + 1] = F[1];
        s_net[o * 60 + kk * 3 + 2] = F[2];
    }
    __syncthreads();

    {
        int og = tid >> 2;
        int kg = tid & 3;
        float acc[2][5][3] = {};
        for (int c = 0; c < 64; c++) {
            float w0 = s_W2T[c * 65 + og * 2 + 0];
            float w1 = s_W2T[c * 65 + og * 2 + 1];
#pragma unroll
            for (int q = 0; q < 5; q++) {
                int kk = kg * 5 + q;
                float n0 = s_net[c * 60 + kk * 3 + 0];
                float n1 = s_net[c * 60 + kk * 3 + 1];
                float n2 = s_net[c * 60 + kk * 3 + 2];
                acc[0][q][0] += w0 * n0; acc[0][q][1] += w0 * n1; acc[0][q][2] += w0 * n2;
                acc[1][q][0] += w1 * n0; acc[1][q][1] += w1 * n1; acc[1][q][2] += w1 * n2;
            }
        }
#pragma unroll
        for (int r = 0; r < 2; r++)
#pragma unroll
            for (int q = 0; q < 5; q++) {
                int o = og * 2 + r, kk = kg * 5 + q;
                s_dot[o * 20 + kk] =
                    s_net[o * 60 + kk * 3 + 0] * acc[r][q][0] +
                    s_net[o * 60 + kk * 3 + 1] * acc[r][q][1] +
                    s_net[o * 60 + kk * 3 + 2] * acc[r][q][2];
            }
    }
    __syncthreads();

    if (tid < 64) {
        int o = tid;
        int bk = 0; float bv = s_dot[o * 20];
#pragma unroll
        for (int kk = 1; kk < K_; kk++) {
            float v = s_dot[o * 20 + kk];
            if (v > bv) { bv = v; bk = kk; }
        }
#pragma unroll
        for (int v = 0; v < 3; v++)
            outp[(((size_t)b * 64 + o) * 3 + v) * N_ + n] = s_net[o * 60 + bk * 3 + v];
    }
}

// ---------------- 3xTF32 mma.sync batched GEMM (pre-split hi/lo smem) ------------
// Y[b] (Co x 12288) (+)= W (Co x Ci, row stride ldw) @ X[b] (Ci x 12288) (+ bias)
// CTA tile 128x128, warp tile 64x32 (2x4 warps), mma m16n8k8 tf32, 3x split.
// hi/lo split done ONCE per element at smem-fill; mainloop is pure LDS + HMMA.
#define SWH_OFF 0
#define SWL_OFF (2 * 128 * 20)
#define SXH_OFF (SWL_OFF + 2 * 128 * 20)
#define SXL_OFF (SXH_OFF + 2 * 16 * 136)
#define GEMM_SMEM ((SXL_OFF + 2 * 16 * 136) * 4)

__global__ void __launch_bounds__(256) gemm_mma(
    const float* __restrict__ W, const float* __restrict__ X,
    float* __restrict__ Y, const float* __restrict__ bias,
    int Co, int Ci, int ldw, int accflag) {
    extern __shared__ float smem[];
    float* sWh = smem + SWH_OFF;  // [2][128][20]
    float* sWl = smem + SWL_OFF;
    float* sXh = smem + SXH_OFF;  // [2][16][136]
    float* sXl = smem + SXL_OFF;

    int tid = threadIdx.x;
    int wid = tid >> 5, lane = tid & 31;
    int g = lane >> 2, tig = lane & 3;
    int warpM = wid & 1;    // 0..1 -> 64 rows each
    int warpN = wid >> 1;   // 0..3 -> 32 cols each
    int b = blockIdx.z;
    int m0 = blockIdx.x * 128;
    int o0 = blockIdx.y * 128;
    const float* Xb = X + (size_t)b * Ci * M_;
    float* Yb = Y + (size_t)b * Co * M_;

    // fixed per-thread load coords
    int aw_o[2], aw_k[2], bx_k[2], bx_m[2];
#pragma unroll
    for (int r = 0; r < 2; r++) {
        int i = r * 256 + tid;
        aw_o[r] = i >> 2;        // 0..127
        aw_k[r] = (i & 3) * 4;   // 0,4,8,12
        bx_k[r] = i >> 5;        // 0..15
        bx_m[r] = (i & 31) * 4;  // 0..124
    }

    float c[4][4][4];
#pragma unroll
    for (int i = 0; i < 4; i++)
#pragma unroll
        for (int j = 0; j < 4; j++)
#pragma unroll
            for (int q = 0; q < 4; q++) c[i][j][q] = 0.0f;

    float4 aw[2], bx[2];

#define LDG_TILE(kt)                                                              \
    {                                                                             \
        _Pragma("unroll")                                                         \
        for (int r = 0; r < 2; r++) {                                             \
            aw[r] = *reinterpret_cast<const float4*>(                             \
                &W[(size_t)(o0 + aw_o[r]) * ldw + (kt) + aw_k[r]]);               \
            bx[r] = *reinterpret_cast<const float4*>(                             \
                &Xb[(size_t)((kt) + bx_k[r]) * M_ + m0 + bx_m[r]]);               \
        }                                                                         \
    }

#define CVT_STS(s)                                                                \
    {                                                                             \
        _Pragma("unroll")                                                         \
        for (int r = 0; r < 2; r++) {                                             \
            float4 h, l;                                                          \
            h.x = __uint_as_float(cvt_tf32(aw[r].x)); l.x = __uint_as_float(cvt_tf32(aw[r].x - h.x)); \
            h.y = __uint_as_float(cvt_tf32(aw[r].y)); l.y = __uint_as_float(cvt_tf32(aw[r].y - h.y)); \
            h.z = __uint_as_float(cvt_tf32(aw[r].z)); l.z = __uint_as_float(cvt_tf32(aw[r].z - h.z)); \
            h.w = __uint_as_float(cvt_tf32(aw[r].w)); l.w = __uint_as_float(cvt_tf32(aw[r].w - h.w)); \
            int off = ((s) * 128 + aw_o[r]) * 20 + aw_k[r];                       \
            *reinterpret_cast<float4*>(&sWh[off]) = h;                            \
            *reinterpret_cast<float4*>(&sWl[off]) = l;                            \
            h.x = __uint_as_float(cvt_tf32(bx[r].x)); l.x = __uint_as_float(cvt_tf32(bx[r].x - h.x)); \
            h.y = __uint_as_float(cvt_tf32(bx[r].y)); l.y = __uint_as_float(cvt_tf32(bx[r].y - h.y)); \
            h.z = __uint_as_float(cvt_tf32(bx[r].z)); l.z = __uint_as_float(cvt_tf32(bx[r].z - h.z)); \
            h.w = __uint_as_float(cvt_tf32(bx[r].w)); l.w = __uint_as_float(cvt_tf32(bx[r].w - h.w)); \
            off = ((s) * 16 + bx_k[r]) * 136 + bx_m[r];                           \
            *reinterpret_cast<float4*>(&sXh[off]) = h;                            \
            *reinterpret_cast<float4*>(&sXl[off]) = l;                            \
        }                                                                         \
    }

    int nk = Ci >> 4;
    LDG_TILE(0)
    CVT_STS(0)
    __syncthreads();

    for (int t = 0; t < nk; t++) {
        int s = t & 1;
        if (t + 1 < nk) LDG_TILE((t + 1) << 4)  // overlap global latency with MMA

#pragma unroll
        for (int ks = 0; ks < 2; ks++) {
            int k8 = ks * 8;
            uint32_t ah[4][4], al[4][4];
#pragma unroll
            for (int mt = 0; mt < 4; mt++) {
                int r0 = (s * 128 + warpM * 64 + mt * 16 + g) * 20;
                int r1 = r0 + 8 * 20;
                ah[mt][0] = __float_as_uint(sWh[r0 + k8 + tig]);
                ah[mt][1] = __float_as_uint(sWh[r1 + k8 + tig]);
                ah[mt][2] = __float_as_uint(sWh[r0 + k8 + tig + 4]);
                ah[mt][3] = __float_as_uint(sWh[r1 + k8 + tig + 4]);
                al[mt][0] = __float_as_uint(sWl[r0 + k8 + tig]);
                al[mt][1] = __float_as_uint(sWl[r1 + k8 + tig]);
                al[mt][2] = __float_as_uint(sWl[r0 + k8 + tig + 4]);
                al[mt][3] = __float_as_uint(sWl[r1 + k8 + tig + 4]);
            }
            uint32_t bh[4][2], bl[4][2];
#pragma unroll
            for (int nt = 0; nt < 4; nt++) {
                int col = warpN * 32 + nt * 8 + g;
                int c0 = (s * 16 + k8 + tig) * 136 + col;
                int c1 = c0 + 4 * 136;
                bh[nt][0] = __float_as_uint(sXh[c0]);
                bh[nt][1] = __float_as_uint(sXh[c1]);
                bl[nt][0] = __float_as_uint(sXl[c0]);
                bl[nt][1] = __float_as_uint(sXl[c1]);
            }
#pragma unroll
            for (int mt = 0; mt < 4; mt++)
#pragma unroll
                for (int nt = 0; nt < 4; nt++) {
#define MMA(A, Bv)                                                                \
    asm volatile(                                                                 \
        "mma.sync.aligned.m16n8k8.row.col.f32.tf32.tf32.f32 "                     \
        "{%0,%1,%2,%3}, {%4,%5,%6,%7}, {%8,%9}, {%0,%1,%2,%3};"                   \
        : "+f"(c[mt][nt][0]), "+f"(c[mt][nt][1]),                                 \
          "+f"(c[mt][nt][2]), "+f"(c[mt][nt][3])                                  \
        : "r"(A[mt][0]), "r"(A[mt][1]), "r"(A[mt][2]), "r"(A[mt][3]),             \
          "r"(Bv[nt][0]), "r"(Bv[nt][1]))
                    MMA(ah, bh);
                    MMA(ah, bl);
                    MMA(al, bh);
#undef MMA
                }
        }
        if (t + 1 < nk) {
            __syncthreads();       // everyone done reading stage s^1 (from iter t-1)
            CVT_STS(s ^ 1)
        }
        __syncthreads();
    }
#undef LDG_TILE
#undef CVT_STS

    // epilogue: c0=(g,2tig) c1=(g,2tig+1) c2=(g+8,2tig) c3=(g+8,2tig+1)
    int v = m0 >> 12;  // 128-col tiles never straddle a vec-component boundary
#pragma unroll
    for (int mt = 0; mt < 4; mt++) {
        int o = o0 + warpM * 64 + mt * 16 + g;
        float bv0 = bias ? bias[((size_t)b * Co + o) * 3 + v] : 0.0f;
        float bv1 = bias ? bias[((size_t)b * Co + o + 8) * 3 + v] : 0.0f;
#pragma unroll
        for (int nt = 0; nt < 4; nt++) {
            size_t col = m0 + warpN * 32 + nt * 8 + 2 * tig;
            float2* p0 = reinterpret_cast<float2*>(&Yb[(size_t)o * M_ + col]);
            float2* p1 = reinterpret_cast<float2*>(&Yb[(size_t)(o + 8) * M_ + col]);
            float2 v0 = make_float2(c[mt][nt][0] + bv0, c[mt][nt][1] + bv0);
            float2 v1 = make_float2(c[mt][nt][2] + bv1, c[mt][nt][3] + bv1);
            if (accflag) {
                float2 o0v = *p0, o1v = *p1;
                v0.x += o0v.x; v0.y += o0v.y; v1.x += o1v.x; v1.y += o1v.y;
            }
            *p0 = v0;
            *p1 = v1;
        }
    }
}

// ---------------- vn_leaky (float4): h = leaky(x, d) IN PLACE into d -------------
// x channels [0,Cx) from x buffer, [Cx,C) broadcast from pooled.
__global__ void __launch_bounds__(256) leaky_kernel(
    const float* __restrict__ x, const float* __restrict__ pooled,
    float* __restrict__ d, int C, int Cx) {
    int b = blockIdx.y;
    int e = blockIdx.x * 256 + threadIdx.x;  // over C*N/4
    int n = (e & 1023) * 4;
    int c = e >> 10;
    float4 x0, x1, x2;
    if (c < Cx) {
        size_t base = ((size_t)(b * Cx + c) * 3) * N_ + n;
        x0 = *reinterpret_cast<const float4*>(&x[base]);
        x1 = *reinterpret_cast<const float4*>(&x[base + N_]);
        x2 = *reinterpret_cast<const float4*>(&x[base + 2 * N_]);
    } else {
        const float* p = pooled + (size_t)(b * 128 + (c - Cx)) * 3;
        x0 = make_float4(p[0], p[0], p[0], p[0]);
        x1 = make_float4(p[1], p[1], p[1], p[1]);
        x2 = make_float4(p[2], p[2], p[2], p[2]);
    }
    size_t db = ((size_t)(b * C + c) * 3) * N_ + n;
    float4 d0 = *reinterpret_cast<float4*>(&d[db]);
    float4 d1 = *reinterpret_cast<float4*>(&d[db + N_]);
    float4 d2 = *reinterpret_cast<float4*>(&d[db + 2 * N_]);
#define LEAKY1(X0, X1, X2, D0, D1, D2)                                   \
    {                                                                    \
        float dot = X0 * D0 + X1 * D1 + X2 * D2;                         \
        if (dot < 0.0f) {                                                \
            float s = dot / (D0 * D0 + D1 * D1 + D2 * D2 + 1e-6f);       \
            X0 -= s * D0; X1 -= s * D1; X2 -= s * D2;                    \
        }                                                                \
        D0 = X0; D1 = X1; D2 = X2;                                       \
    }
    LEAKY1(x0.x, x1.x, x2.x, d0.x, d1.x, d2.x)
    LEAKY1(x0.y, x1.y, x2.y, d0.y, d1.y, d2.y)
    LEAKY1(x0.z, x1.z, x2.z, d0.z, d1.z, d2.z)
    LEAKY1(x0.w, x1.w, x2.w, d0.w, d1.w, d2.w)
#undef LEAKY1
    *reinterpret_cast<float4*>(&d[db]) = d0;
    *reinterpret_cast<float4*>(&d[db + N_]) = d1;
    *reinterpret_cast<float4*>(&d[db + 2 * N_]) = d2;
}

// ---------------- vn_max_pool over N: argmax of <net,d>, gather ------------------
__global__ void __launch_bounds__(256) pool_reduce(
    const float* __restrict__ net, const float* __restrict__ d,
    float* __restrict__ pooled) {
    __shared__ float sv[256];
    __shared__ int si[256];
    int c = blockIdx.x, b = blockIdx.y, tid = threadIdx.x;
    size_t base = ((size_t)(b * 128 + c) * 3) * N_;
    float bv = -3.4e38f; int bi = 0;
    for (int n = tid; n < N_; n += 256) {
        float dot = net[base + n] * d[base + n]
                  + net[base + N_ + n] * d[base + N_ + n]
                  + net[base + 2 * N_ + n] * d[base + 2 * N_ + n];
        if (dot > bv) { bv = dot; bi = n; }
    }
    sv[tid] = bv; si[tid] = bi;
    __syncthreads();
    for (int s = 128; s > 0; s >>= 1) {
        if (tid < s) {
            float v2 = sv[tid + s]; int i2 = si[tid + s];
            if (v2 > sv[tid] || (v2 == sv[tid] && i2 < si[tid])) {
                sv[tid] = v2; si[tid] = i2;  // first-index-wins = jnp.argmax
            }
        }
        __syncthreads();
    }
    if (tid < 3) pooled[(size_t)(b * 128 + c) * 3 + tid] = net[base + (size_t)tid * N_ + si[0]];
}

// ---------------- bias from broadcast-concat: bias[b,o,v] = W[o,128:] . pooled ---
__global__ void bias_kernel(const float* __restrict__ W, const float* __restrict__ pooled,
                            float* __restrict__ bias, int Co) {
    __shared__ float sp[128];
    int b = blockIdx.x, v = blockIdx.y, o = threadIdx.x;
    if (o < 128) sp[o] = pooled[(size_t)(b * 128 + o) * 3 + v];
    __syncthreads();
    const float* w = W + (size_t)o * 256 + 128;
    float acc = 0.0f;
#pragma unroll 8
    for (int c = 0; c < 128; c++) acc += w[c] * sp[c];
    bias[((size_t)b * Co + o) * 3 + v] = acc;
}

// ---------------- final head: c = fcc @ leaky(nt, actc @ nt) ---------------------
__global__ void __launch_bounds__(128) head_kernel(
    const float* __restrict__ pooled, const float* __restrict__ Wa,
    const float* __restrict__ Wc, float* __restrict__ out) {
    __shared__ float s_nt[384], s_h[384];
    int b = blockIdx.x, o = threadIdx.x;
    for (int i = o; i < 384; i += 128) s_nt[i] = pooled[b * 384 + i];
    __syncthreads();
    float d0 = 0, d1 = 0, d2 = 0;
    for (int c = 0; c < 128; c++) {
        float w = Wa[o * 128 + c];
        d0 += w * s_nt[c * 3]; d1 += w * s_nt[c * 3 + 1]; d2 += w * s_nt[c * 3 + 2];
    }
    float x0 = s_nt[o * 3], x1 = s_nt[o * 3 + 1], x2 = s_nt[o * 3 + 2];
    float dot = x0 * d0 + x1 * d1 + x2 * d2;
    if (dot < 0.0f) {
        float s = dot / (d0 * d0 + d1 * d1 + d2 * d2 + 1e-6f);
        x0 -= s * d0; x1 -= s * d1; x2 -= s * d2;
    }
    s_h[o * 3] = x0; s_h[o * 3 + 1] = x1; s_h[o * 3 + 2] = x2;
    __syncthreads();
    if (o < 64) {
        float a0 = 0, a1 = 0, a2 = 0;
        for (int c = 0; c < 128; c++) {
            float w = Wc[o * 128 + c];
            a0 += w * s_h[c * 3]; a1 += w * s_h[c * 3 + 1]; a2 += w * s_h[c * 3 + 2];
        }
        out[b * 192 + o * 3 + 0] = a0;
        out[b * 192 + o * 3 + 1] = a1;
        out[b * 192 + o * 3 + 2] = a2;
    }
}

static void launch_gemm(const float* W, const float* X, float* Y, const float* bias,
                        int Co, int Ci, int ldw, int accflag) {
    gemm_mma<<<dim3(96, Co / 128, B_), 256, GEMM_SMEM>>>(W, X, Y, bias, Co, Ci, ldw, accflag);
}

extern "C" void kernel_launch(void* const* d_in, const int* in_sizes, int n_in,
                              void* d_out, int out_size) {
    const float* pc      = (const float*)d_in[0];
    const float* conv_Wf = (const float*)d_in[1];
    const float* conv_Wd = (const float*)d_in[2];
    const float* pp_Wd   = (const float*)d_in[3];
    const float* fc_pos  = (const float*)d_in[4];
    const float* a0      = (const float*)d_in[5];
    const float* f0      = (const float*)d_in[6];
    const float* a1      = (const float*)d_in[7];
    const float* f1      = (const float*)d_in[8];
    const float* sc      = (const float*)d_in[9];
    const float* poolWd  = (const float*)d_in[10];
    const float* actc    = (const float*)d_in[11];
    const float* fcc     = (const float*)d_in[12];
    float* out = (float*)d_out;

    cudaFuncSetAttribute(gemm_mma, cudaFuncAttributeMaxDynamicSharedMemorySize, GEMM_SMEM);

    float *pool64, *act256, *d0b, *net1, *d1b, *netA, *netB, *pooled, *biasA, *biasS;
    int* knn;
    cudaGetSymbolAddress((void**)&pool64, g_pool64);
    cudaGetSymbolAddress((void**)&act256, g_act256);
    cudaGetSymbolAddress((void**)&d0b,    g_d0);
    cudaGetSymbolAddress((void**)&net1,   g_net1);
    cudaGetSymbolAddress((void**)&d1b,    g_d1);
    cudaGetSymbolAddress((void**)&netA,   g_netA);
    cudaGetSymbolAddress((void**)&netB,   g_netB);
    cudaGetSymbolAddress((void**)&pooled, g_pooled);
    cudaGetSymbolAddress((void**)&biasA,  g_biasA);
    cudaGetSymbolAddress((void**)&biasS,  g_biasS);
    cudaGetSymbolAddress((void**)&knn,    g_knn);

    knn_kernel<<<dim3(N_ / 128, B_), 128>>>(pc, knn);
    edge_conv_kernel<<<dim3(N_, B_), 128>>>(pc, knn, conv_Wf, conv_Wd, pp_Wd, pool64);
    // fc_pos: [256,64] @ [64, 12288]
    launch_gemm(fc_pos, pool64, act256, nullptr, 256, 64, 64, 0);

    float* nets[2] = {netA, netB};
    const float* x = act256;
    for (int i = 0; i < 5; i++) {
        const float* a0i = a0 + i * 65536;
        const float* f0i = f0 + i * 32768;
        const float* a1i = a1 + i * 16384;
        const float* f1i = f1 + i * 16384;
        const float* sci = sc + i * 32768;
        float* outn = nets[i & 1];
        int Cx = (i == 0) ? 256 : 128;
        const float* biasAp = (i == 0) ? nullptr : biasA;
        const float* biasSp = (i == 0) ? nullptr : biasS;
        if (i > 0) {
            bias_kernel<<<dim3(B_, 3), 256>>>(a0i, pooled, biasA, 256);
            bias_kernel<<<dim3(B_, 3), 128>>>(sci, pooled, biasS, 128);
        }
        // d0 = a0[:, :Cx] @ x (+ biasA)
        launch_gemm(a0i, x, d0b, biasAp, 256, Cx, 256, 0);
        // h = leaky(concat(x,pooled), d0) in place (256 ch)
        leaky_kernel<<<dim3(256 * 4, B_), 256>>>(x, pooled, d0b, 256, Cx);
        // net1 = f0 @ h
        launch_gemm(f0i, d0b, net1, nullptr, 128, 256, 256, 0);
        // d1 = a1 @ net1; h1 = leaky(net1, d1) in place
        launch_gemm(a1i, net1, d1b, nullptr, 128, 128, 128, 0);
        leaky_kernel<<<dim3(128 * 4, B_), 256>>>(net1, pooled, d1b, 128, 128);
        // out = sc[:, :Cx] @ x (+ biasS); out += f1 @ h1
        launch_gemm(sci, x, outn, biasSp, 128, Cx, 256, 0);
        launch_gemm(f1i, d1b, outn, nullptr, 128, 128, 128, 1);
        // pooled = vn_max_pool(out, pool_Wd[i]) over N
        launch_gemm(poolWd + i * 16384, outn, d1b, nullptr, 128, 128, 128, 0);
        pool_reduce<<<dim3(128, B_), 256>>>(outn, d1b, pooled);
        x = outn;
    }
    head_kernel<<<B_, 128>>>(pooled, actc, fcc, out);
}

// round 11
// speedup vs baseline: 1.0871x; 1.0871x over previous
#include <cuda_runtime.h>
#include <cstdint>

#define B_ 4
#define N_ 4096
#define K_ 20
#define M_ 12288  // 3*N_

// ---------------- scratch (device globals; no runtime allocation) ----------------
__device__ float g_pool64[B_ * 64 * 3 * N_];
__device__ float g_act256[B_ * 256 * 3 * N_];
__device__ float g_d0[B_ * 256 * 3 * N_];
__device__ float g_net1[B_ * 128 * 3 * N_];
__device__ float g_d1[B_ * 128 * 3 * N_];
__device__ float g_netA[B_ * 128 * 3 * N_];
__device__ float g_netB[B_ * 128 * 3 * N_];
__device__ float g_pooled[B_ * 128 * 3];
__device__ float g_biasA[B_ * 256 * 3];
__device__ float g_biasS[B_ * 128 * 3];
__device__ int   g_knn[B_ * N_ * K_];

__device__ __forceinline__ uint32_t cvt_tf32(float x) {
    uint32_t r;
    asm("cvt.rna.tf32.f32 %0, %1;" : "=r"(r) : "f"(x));
    return r;
}

// ---------------- KNN: brute-force top-20 by neg squared distance ----------------
__global__ void __launch_bounds__(128) knn_kernel(const float* __restrict__ pc,
                                                  int* __restrict__ knn) {
    __shared__ float s_pts[N_ * 3];  // 48KB
    int b = blockIdx.y;
    int tid = threadIdx.x;
    const float* pb = pc + (size_t)b * N_ * 3;
    for (int i = tid; i < N_ * 3; i += 128) s_pts[i] = pb[i];
    __syncthreads();

    int n = blockIdx.x * 128 + tid;
    float qx = s_pts[n * 3 + 0], qy = s_pts[n * 3 + 1], qz = s_pts[n * 3 + 2];
    float sqn = qx * qx + qy * qy + qz * qz;

    float best[K_];
    int bidx[K_];
#pragma unroll
    for (int i = 0; i < K_; i++) { best[i] = -1e30f; bidx[i] = 0; }
    float kmin = -1e30f;

    for (int m = 0; m < N_; m++) {
        float mx = s_pts[m * 3 + 0], my = s_pts[m * 3 + 1], mz = s_pts[m * 3 + 2];
        float inner = qx * mx + qy * my + qz * mz;
        float sqm = mx * mx + my * my + mz * mz;
        float v = 2.0f * inner - sqn - sqm;
        if (v > kmin) {  // strict: ties keep earlier index (matches lax.top_k)
            int j = K_ - 1;
            while (j > 0 && best[j - 1] < v) {
                best[j] = best[j - 1]; bidx[j] = bidx[j - 1]; j--;
            }
            best[j] = v; bidx[j] = m;
            kmin = best[K_ - 1];
        }
    }
    int* o = knn + ((size_t)b * N_ + n) * K_;
#pragma unroll
    for (int i = 0; i < K_; i++) o[i] = bidx[i];
}

// ---------------- edge conv (3->64) + vn_leaky + max-pool over k ----------------
__global__ void __launch_bounds__(128) edge_conv_kernel(
    const float* __restrict__ pc, const int* __restrict__ knn,
    const float* __restrict__ Wf, const float* __restrict__ Wd,
    const float* __restrict__ W2, float* __restrict__ outp) {
    __shared__ float s_net[64 * 60];   // [o][kk][v]
    __shared__ float s_W2T[64 * 65];   // transposed, padded: [c][o]
    __shared__ float s_dot[64 * 20];
    __shared__ float s_e[K_][3], s_cr[K_][3], s_x[3];
    __shared__ float s_Wf[192], s_Wd[192];

    int n = blockIdx.x, b = blockIdx.y;
    int tid = threadIdx.x;  // 128

    for (int i = tid; i < 192; i += 128) { s_Wf[i] = Wf[i]; s_Wd[i] = Wd[i]; }
    for (int i = tid; i < 4096; i += 128) {
        int o = i >> 6, c = i & 63;
        s_W2T[c * 65 + o] = W2[i];
    }
    if (tid < 3) s_x[tid] = pc[((size_t)b * N_ + n) * 3 + tid];
    __syncthreads();

    if (tid < K_) {
        int m = knn[((size_t)b * N_ + n) * K_ + tid];
        const float* pm = pc + ((size_t)b * N_ + m) * 3;
        float nx = pm[0], ny = pm[1], nz = pm[2];
        float x0 = s_x[0], x1 = s_x[1], x2 = s_x[2];
        s_e[tid][0] = nx - x0; s_e[tid][1] = ny - x1; s_e[tid][2] = nz - x2;
        s_cr[tid][0] = ny * x2 - nz * x1;  // cross(nbr, x)
        s_cr[tid][1] = nz * x0 - nx * x2;
        s_cr[tid][2] = nx * x1 - ny * x0;
    }
    __syncthreads();

    for (int t = tid; t < 64 * K_; t += 128) {
        int o = t / K_, kk = t % K_;
        float wf0 = s_Wf[o * 3 + 0], wf1 = s_Wf[o * 3 + 1], wf2 = s_Wf[o * 3 + 2];
        float wd0 = s_Wd[o * 3 + 0], wd1 = s_Wd[o * 3 + 1], wd2 = s_Wd[o * 3 + 2];
        float F[3], D[3];
#pragma unroll
        for (int v = 0; v < 3; v++) {
            float e = s_e[kk][v], xx = s_x[v], cr = s_cr[kk][v];
            F[v] = wf0 * e + wf1 * xx + wf2 * cr;
            D[v] = wd0 * e + wd1 * xx + wd2 * cr;
        }
        float dot = F[0] * D[0] + F[1] * D[1] + F[2] * D[2];
        if (dot < 0.0f) {
            float s = dot / (D[0] * D[0] + D[1] * D[1] + D[2] * D[2] + 1e-6f);
            F[0] -= s * D[0]; F[1] -= s * D[1]; F[2] -= s * D[2];
        }
        s_net[o * 60 + kk * 3 + 0] = F[0];
        s_net[o * 60 + kk * 3 + 1] = F[1];
        s_net[o * 60 + kk * 3 + 2] = F[2];
    }
    __syncthreads();

    {
        int og = tid >> 2;
        int kg = tid & 3;
        float acc[2][5][3] = {};
        for (int c = 0; c < 64; c++) {
            float w0 = s_W2T[c * 65 + og * 2 + 0];
            float w1 = s_W2T[c * 65 + og * 2 + 1];
#pragma unroll
            for (int q = 0; q < 5; q++) {
                int kk = kg * 5 + q;
                float n0 = s_net[c * 60 + kk * 3 + 0];
                float n1 = s_net[c * 60 + kk * 3 + 1];
                float n2 = s_net[c * 60 + kk * 3 + 2];
                acc[0][q][0] += w0 * n0; acc[0][q][1] += w0 * n1; acc[0][q][2] += w0 * n2;
                acc[1][q][0] += w1 * n0; acc[1][q][1] += w1 * n1; acc[1][q][2] += w1 * n2;
            }
        }
#pragma unroll
        for (int r = 0; r < 2; r++)
#pragma unroll
            for (int q = 0; q < 5; q++) {
                int o = og * 2 + r, kk = kg * 5 + q;
                s_dot[o * 20 + kk] =
                    s_net[o * 60 + kk * 3 + 0] * acc[r][q][0] +
                    s_net[o * 60 + kk * 3 + 1] * acc[r][q][1] +
                    s_net[o * 60 + kk * 3 + 2] * acc[r][q][2];
            }
    }
    __syncthreads();

    if (tid < 64) {
        int o = tid;
        int bk = 0; float bv = s_dot[o * 20];
#pragma unroll
        for (int kk = 1; kk < K_; kk++) {
            float v = s_dot[o * 20 + kk];
            if (v > bv) { bv = v; bk = kk; }
        }
#pragma unroll
        for (int v = 0; v < 3; v++)
            outp[(((size_t)b * 64 + o) * 3 + v) * N_ + n] = s_net[o * 60 + bk * 3 + v];
    }
}

// ---------------- 3xTF32 mma.sync batched GEMM (hybrid: A pre-split in smem) -----
// Y[b] (Co x 12288) (+)= W (Co x Ci, row stride ldw) @ X[b] (Ci x 12288) (+ bias)
// CTA tile 128x128, warp tile 64x32 (2x4 warps), mma m16n8k8 tf32, 3x split.
// W hi/lo split once at fill (4x read-redundancy removed); X raw via cp.async,
// B conversion in registers (only 2x redundant).
#define SWH_OFF 0                       // [2][128][20]
#define SWL_OFF (2 * 128 * 20)          // [2][128][20]
#define SX_OFF  (SWL_OFF + 2 * 128 * 20)  // [2][16][136]
#define GEMM_SMEM ((SX_OFF + 2 * 16 * 136) * 4)

__global__ void __launch_bounds__(256, 2) gemm_mma(
    const float* __restrict__ W, const float* __restrict__ X,
    float* __restrict__ Y, const float* __restrict__ bias,
    int Co, int Ci, int ldw, int accflag) {
    extern __shared__ float smem[];
    float* sWh = smem + SWH_OFF;
    float* sWl = smem + SWL_OFF;
    float* sX  = smem + SX_OFF;

    int tid = threadIdx.x;
    int wid = tid >> 5, lane = tid & 31;
    int g = lane >> 2, tig = lane & 3;
    int warpM = wid & 1;    // 0..1 -> 64 rows each
    int warpN = wid >> 1;   // 0..3 -> 32 cols each
    int b = blockIdx.z;
    int m0 = blockIdx.x * 128;
    int o0 = blockIdx.y * 128;
    const float* Xb = X + (size_t)b * Ci * M_;
    float* Yb = Y + (size_t)b * Co * M_;

    // fixed per-thread load coords
    int aw_o[2], aw_k[2], bx_k[2], bx_m[2];
#pragma unroll
    for (int r = 0; r < 2; r++) {
        int i = r * 256 + tid;
        aw_o[r] = i >> 2;        // 0..127
        aw_k[r] = (i & 3) * 4;   // 0,4,8,12
        bx_k[r] = i >> 5;        // 0..15
        bx_m[r] = (i & 31) * 4;  // 0..124
    }

    float c[4][4][4];
#pragma unroll
    for (int i = 0; i < 4; i++)
#pragma unroll
        for (int j = 0; j < 4; j++)
#pragma unroll
            for (int q = 0; q < 4; q++) c[i][j][q] = 0.0f;

    float4 aw[2];

#define LDG_W(kt)                                                                 \
    {                                                                             \
        _Pragma("unroll")                                                         \
        for (int r = 0; r < 2; r++)                                               \
            aw[r] = *reinterpret_cast<const float4*>(                             \
                &W[(size_t)(o0 + aw_o[r]) * ldw + (kt) + aw_k[r]]);               \
    }

#define CP_X(kt, s)                                                               \
    {                                                                             \
        _Pragma("unroll")                                                         \
        for (int r = 0; r < 2; r++) {                                             \
            unsigned int dst = (unsigned int)__cvta_generic_to_shared(            \
                &sX[((s) * 16 + bx_k[r]) * 136 + bx_m[r]]);                       \
            const float* src = &Xb[(size_t)((kt) + bx_k[r]) * M_ + m0 + bx_m[r]]; \
            asm volatile("cp.async.ca.shared.global [%0], [%1], 16;" ::           \
                         "r"(dst), "l"(src));                                     \
        }                                                                         \
        asm volatile("cp.async.commit_group;");                                   \
    }

#define CVT_STS_W(s)                                                              \
    {                                                                             \
        _Pragma("unroll")                                                         \
        for (int r = 0; r < 2; r++) {                                             \
            float4 h, l;                                                          \
            h.x = __uint_as_float(cvt_tf32(aw[r].x)); l.x = __uint_as_float(cvt_tf32(aw[r].x - h.x)); \
            h.y = __uint_as_float(cvt_tf32(aw[r].y)); l.y = __uint_as_float(cvt_tf32(aw[r].y - h.y)); \
            h.z = __uint_as_float(cvt_tf32(aw[r].z)); l.z = __uint_as_float(cvt_tf32(aw[r].z - h.z)); \
            h.w = __uint_as_float(cvt_tf32(aw[r].w)); l.w = __uint_as_float(cvt_tf32(aw[r].w - h.w)); \
            int off = ((s) * 128 + aw_o[r]) * 20 + aw_k[r];                       \
            *reinterpret_cast<float4*>(&sWh[off]) = h;                            \
            *reinterpret_cast<float4*>(&sWl[off]) = l;                            \
        }                                                                         \
    }

    int nk = Ci >> 4;
    LDG_W(0)
    CP_X(0, 0)
    CVT_STS_W(0)
    asm volatile("cp.async.wait_group 0;");
    __syncthreads();

    for (int t = 0; t < nk; t++) {
        int s = t & 1;
        if (t + 1 < nk) {
            LDG_W((t + 1) << 4)
            CP_X((t + 1) << 4, s ^ 1)   // stage s^1 readers finished at end of t-1
        }

#pragma unroll
        for (int ks = 0; ks < 2; ks++) {
            int k8 = ks * 8;
            // A-hi fragments (pure LDS, no ALU)
            uint32_t ah[4][4];
#pragma unroll
            for (int mt = 0; mt < 4; mt++) {
                int r0 = (s * 128 + warpM * 64 + mt * 16 + g) * 20;
                int r1 = r0 + 8 * 20;
                ah[mt][0] = __float_as_uint(sWh[r0 + k8 + tig]);
                ah[mt][1] = __float_as_uint(sWh[r1 + k8 + tig]);
                ah[mt][2] = __float_as_uint(sWh[r0 + k8 + tig + 4]);
                ah[mt][3] = __float_as_uint(sWh[r1 + k8 + tig + 4]);
            }
            // B fragments: raw LDS + in-register hi/lo split (2x redundant only)
            uint32_t bh[4][2], bl[4][2];
#pragma unroll
            for (int nt = 0; nt < 4; nt++) {
                int col = warpN * 32 + nt * 8 + g;
                float v0 = sX[(s * 16 + k8 + tig) * 136 + col];
                float v1 = sX[(s * 16 + k8 + tig + 4) * 136 + col];
                bh[nt][0] = cvt_tf32(v0); bl[nt][0] = cvt_tf32(v0 - __uint_as_float(bh[nt][0]));
                bh[nt][1] = cvt_tf32(v1); bl[nt][1] = cvt_tf32(v1 - __uint_as_float(bh[nt][1]));
            }
#define MMA(A, Bv, mt, nt)                                                        \
    asm volatile(                                                                 \
        "mma.sync.aligned.m16n8k8.row.col.f32.tf32.tf32.f32 "                     \
        "{%0,%1,%2,%3}, {%4,%5,%6,%7}, {%8,%9}, {%0,%1,%2,%3};"                   \
        : "+f"(c[mt][nt][0]), "+f"(c[mt][nt][1]),                                 \
          "+f"(c[mt][nt][2]), "+f"(c[mt][nt][3])                                  \
        : "r"(A[mt][0]), "r"(A[mt][1]), "r"(A[mt][2]), "r"(A[mt][3]),             \
          "r"(Bv[nt][0]), "r"(Bv[nt][1]))
#pragma unroll
            for (int mt = 0; mt < 4; mt++)
#pragma unroll
                for (int nt = 0; nt < 4; nt++) {
                    MMA(ah, bh, mt, nt);
                    MMA(ah, bl, mt, nt);
                }
            // A-lo fragments (reuse ah registers after bl is consumed)
            uint32_t al[4][4];
#pragma unroll
            for (int mt = 0; mt < 4; mt++) {
                int r0 = (s * 128 + warpM * 64 + mt * 16 + g) * 20;
                int r1 = r0 + 8 * 20;
                al[mt][0] = __float_as_uint(sWl[r0 + k8 + tig]);
                al[mt][1] = __float_as_uint(sWl[r1 + k8 + tig]);
                al[mt][2] = __float_as_uint(sWl[r0 + k8 + tig + 4]);
                al[mt][3] = __float_as_uint(sWl[r1 + k8 + tig + 4]);
            }
#pragma unroll
            for (int mt = 0; mt < 4; mt++)
#pragma unroll
                for (int nt = 0; nt < 4; nt++) MMA(al, bh, mt, nt);
#undef MMA
        }
        if (t + 1 < nk) {
            __syncthreads();            // all reads of stage s^1 from t-1 done; s reads done
            CVT_STS_W(s ^ 1)
            asm volatile("cp.async.wait_group 0;");
        }
        __syncthreads();
    }
#undef LDG_W
#undef CP_X
#undef CVT_STS_W

    // epilogue: c0=(g,2tig) c1=(g,2tig+1) c2=(g+8,2tig) c3=(g+8,2tig+1)
    int v = m0 >> 12;  // 128-col tiles never straddle a vec-component boundary
#pragma unroll
    for (int mt = 0; mt < 4; mt++) {
        int o = o0 + warpM * 64 + mt * 16 + g;
        float bv0 = bias ? bias[((size_t)b * Co + o) * 3 + v] : 0.0f;
        float bv1 = bias ? bias[((size_t)b * Co + o + 8) * 3 + v] : 0.0f;
#pragma unroll
        for (int nt = 0; nt < 4; nt++) {
            size_t col = m0 + warpN * 32 + nt * 8 + 2 * tig;
            float2* p0 = reinterpret_cast<float2*>(&Yb[(size_t)o * M_ + col]);
            float2* p1 = reinterpret_cast<float2*>(&Yb[(size_t)(o + 8) * M_ + col]);
            float2 v0 = make_float2(c[mt][nt][0] + bv0, c[mt][nt][1] + bv0);
            float2 v1 = make_float2(c[mt][nt][2] + bv1, c[mt][nt][3] + bv1);
            if (accflag) {
                float2 o0v = *p0, o1v = *p1;
                v0.x += o0v.x; v0.y += o0v.y; v1.x += o1v.x; v1.y += o1v.y;
            }
            *p0 = v0;
            *p1 = v1;
        }
    }
}

// ---------------- vn_leaky (float4): h = leaky(x, d) IN PLACE into d -------------
__global__ void __launch_bounds__(256) leaky_kernel(
    const float* __restrict__ x, const float* __restrict__ pooled,
    float* __restrict__ d, int C, int Cx) {
    int b = blockIdx.y;
    int e = blockIdx.x * 256 + threadIdx.x;  // over C*N/4
    int n = (e & 1023) * 4;
    int c = e >> 10;
    float4 x0, x1, x2;
    if (c < Cx) {
        size_t base = ((size_t)(b * Cx + c) * 3) * N_ + n;
        x0 = *reinterpret_cast<const float4*>(&x[base]);
        x1 = *reinterpret_cast<const float4*>(&x[base + N_]);
        x2 = *reinterpret_cast<const float4*>(&x[base + 2 * N_]);
    } else {
        const float* p = pooled + (size_t)(b * 128 + (c - Cx)) * 3;
        x0 = make_float4(p[0], p[0], p[0], p[0]);
        x1 = make_float4(p[1], p[1], p[1], p[1]);
        x2 = make_float4(p[2], p[2], p[2], p[2]);
    }
    size_t db = ((size_t)(b * C + c) * 3) * N_ + n;
    float4 d0 = *reinterpret_cast<float4*>(&d[db]);
    float4 d1 = *reinterpret_cast<float4*>(&d[db + N_]);
    float4 d2 = *reinterpret_cast<float4*>(&d[db + 2 * N_]);
#define LEAKY1(X0, X1, X2, D0, D1, D2)                                   \
    {                                                                    \
        float dot = X0 * D0 + X1 * D1 + X2 * D2;                         \
        if (dot < 0.0f) {                                                \
            float s = dot / (D0 * D0 + D1 * D1 + D2 * D2 + 1e-6f);       \
            X0 -= s * D0; X1 -= s * D1; X2 -= s * D2;                    \
        }                                                                \
        D0 = X0; D1 = X1; D2 = X2;                                       \
    }
    LEAKY1(x0.x, x1.x, x2.x, d0.x, d1.x, d2.x)
    LEAKY1(x0.y, x1.y, x2.y, d0.y, d1.y, d2.y)
    LEAKY1(x0.z, x1.z, x2.z, d0.z, d1.z, d2.z)
    LEAKY1(x0.w, x1.w, x2.w, d0.w, d1.w, d2.w)
#undef LEAKY1
    *reinterpret_cast<float4*>(&d[db]) = d0;
    *reinterpret_cast<float4*>(&d[db + N_]) = d1;
    *reinterpret_cast<float4*>(&d[db + 2 * N_]) = d2;
}

// ---------------- vn_max_pool over N: argmax of <net,d>, gather ------------------
__global__ void __launch_bounds__(256) pool_reduce(
    const float* __restrict__ net, const float* __restrict__ d,
    float* __restrict__ pooled) {
    __shared__ float sv[256];
    __shared__ int si[256];
    int c = blockIdx.x, b = blockIdx.y, tid = threadIdx.x;
    size_t base = ((size_t)(b * 128 + c) * 3) * N_;
    float bv = -3.4e38f; int bi = 0;
    for (int n = tid; n < N_; n += 256) {
        float dot = net[base + n] * d[base + n]
                  + net[base + N_ + n] * d[base + N_ + n]
                  + net[base + 2 * N_ + n] * d[base + 2 * N_ + n];
        if (dot > bv) { bv = dot; bi = n; }
    }
    sv[tid] = bv; si[tid] = bi;
    __syncthreads();
    for (int s = 128; s > 0; s >>= 1) {
        if (tid < s) {
            float v2 = sv[tid + s]; int i2 = si[tid + s];
            if (v2 > sv[tid] || (v2 == sv[tid] && i2 < si[tid])) {
                sv[tid] = v2; si[tid] = i2;  // first-index-wins = jnp.argmax
            }
        }
        __syncthreads();
    }
    if (tid < 3) pooled[(size_t)(b * 128 + c) * 3 + tid] = net[base + (size_t)tid * N_ + si[0]];
}

// ---------------- bias from broadcast-concat: bias[b,o,v] = W[o,128:] . pooled ---
__global__ void bias_kernel(const float* __restrict__ W, const float* __restrict__ pooled,
                            float* __restrict__ bias, int Co) {
    __shared__ float sp[128];
    int b = blockIdx.x, v = blockIdx.y, o = threadIdx.x;
    if (o < 128) sp[o] = pooled[(size_t)(b * 128 + o) * 3 + v];
    __syncthreads();
    const float* w = W + (size_t)o * 256 + 128;
    float acc = 0.0f;
#pragma unroll 8
    for (int c = 0; c < 128; c++) acc += w[c] * sp[c];
    bias[((size_t)b * Co + o) * 3 + v] = acc;
}

// ---------------- final head: c = fcc @ leaky(nt, actc @ nt) ---------------------
__global__ void __launch_bounds__(128) head_kernel(
    const float* __restrict__ pooled, const float* __restrict__ Wa,
    const float* __restrict__ Wc, float* __restrict__ out) {
    __shared__ float s_nt[384], s_h[384];
    int b = blockIdx.x, o = threadIdx.x;
    for (int i = o; i < 384; i += 128) s_nt[i] = pooled[b * 384 + i];
    __syncthreads();
    float d0 = 0, d1 = 0, d2 = 0;
    for (int c = 0; c < 128; c++) {
        float w = Wa[o * 128 + c];
        d0 += w * s_nt[c * 3]; d1 += w * s_nt[c * 3 + 1]; d2 += w * s_nt[c * 3 + 2];
    }
    float x0 = s_nt[o * 3], x1 = s_nt[o * 3 + 1], x2 = s_nt[o * 3 + 2];
    float dot = x0 * d0 + x1 * d1 + x2 * d2;
    if (dot < 0.0f) {
        float s = dot / (d0 * d0 + d1 * d1 + d2 * d2 + 1e-6f);
        x0 -= s * d0; x1 -= s * d1; x2 -= s * d2;
    }
    s_h[o * 3] = x0; s_h[o * 3 + 1] = x1; s_h[o * 3 + 2] = x2;
    __syncthreads();
    if (o < 64) {
        float a0 = 0, a1 = 0, a2 = 0;
        for (int c = 0; c < 128; c++) {
            float w = Wc[o * 128 + c];
            a0 += w * s_h[c * 3]; a1 += w * s_h[c * 3 + 1]; a2 += w * s_h[c * 3 + 2];
        }
        out[b * 192 + o * 3 + 0] = a0;
        out[b * 192 + o * 3 + 1] = a1;
        out[b * 192 + o * 3 + 2] = a2;
    }
}

static void launch_gemm(const float* W, const float* X, float* Y, const float* bias,
                        int Co, int Ci, int ldw, int accflag) {
    gemm_mma<<<dim3(96, Co / 128, B_), 256, GEMM_SMEM>>>(W, X, Y, bias, Co, Ci, ldw, accflag);
}

extern "C" void kernel_launch(void* const* d_in, const int* in_sizes, int n_in,
                              void* d_out, int out_size) {
    const float* pc      = (const float*)d_in[0];
    const float* conv_Wf = (const float*)d_in[1];
    const float* conv_Wd = (const float*)d_in[2];
    const float* pp_Wd   = (const float*)d_in[3];
    const float* fc_pos  = (const float*)d_in[4];
    const float* a0      = (const float*)d_in[5];
    const float* f0      = (const float*)d_in[6];
    const float* a1      = (const float*)d_in[7];
    const float* f1      = (const float*)d_in[8];
    const float* sc      = (const float*)d_in[9];
    const float* poolWd  = (const float*)d_in[10];
    const float* actc    = (const float*)d_in[11];
    const float* fcc     = (const float*)d_in[12];
    float* out = (float*)d_out;

    cudaFuncSetAttribute(gemm_mma, cudaFuncAttributeMaxDynamicSharedMemorySize, GEMM_SMEM);

    float *pool64, *act256, *d0b, *net1, *d1b, *netA, *netB, *pooled, *biasA, *biasS;
    int* knn;
    cudaGetSymbolAddress((void**)&pool64, g_pool64);
    cudaGetSymbolAddress((void**)&act256, g_act256);
    cudaGetSymbolAddress((void**)&d0b,    g_d0);
    cudaGetSymbolAddress((void**)&net1,   g_net1);
    cudaGetSymbolAddress((void**)&d1b,    g_d1);
    cudaGetSymbolAddress((void**)&netA,   g_netA);
    cudaGetSymbolAddress((void**)&netB,   g_netB);
    cudaGetSymbolAddress((void**)&pooled, g_pooled);
    cudaGetSymbolAddress((void**)&biasA,  g_biasA);
    cudaGetSymbolAddress((void**)&biasS,  g_biasS);
    cudaGetSymbolAddress((void**)&knn,    g_knn);

    knn_kernel<<<dim3(N_ / 128, B_), 128>>>(pc, knn);
    edge_conv_kernel<<<dim3(N_, B_), 128>>>(pc, knn, conv_Wf, conv_Wd, pp_Wd, pool64);
    // fc_pos: [256,64] @ [64, 12288]
    launch_gemm(fc_pos, pool64, act256, nullptr, 256, 64, 64, 0);

    float* nets[2] = {netA, netB};
    const float* x = act256;
    for (int i = 0; i < 5; i++) {
        const float* a0i = a0 + i * 65536;
        const float* f0i = f0 + i * 32768;
        const float* a1i = a1 + i * 16384;
        const float* f1i = f1 + i * 16384;
        const float* sci = sc + i * 32768;
        float* outn = nets[i & 1];
        int Cx = (i == 0) ? 256 : 128;
        const float* biasAp = (i == 0) ? nullptr : biasA;
        const float* biasSp = (i == 0) ? nullptr : biasS;
        if (i > 0) {
            bias_kernel<<<dim3(B_, 3), 256>>>(a0i, pooled, biasA, 256);
            bias_kernel<<<dim3(B_, 3), 128>>>(sci, pooled, biasS, 128);
        }
        // d0 = a0[:, :Cx] @ x (+ biasA)
        launch_gemm(a0i, x, d0b, biasAp, 256, Cx, 256, 0);
        // h = leaky(concat(x,pooled), d0) in place (256 ch)
        leaky_kernel<<<dim3(256 * 4, B_), 256>>>(x, pooled, d0b, 256, Cx);
        // net1 = f0 @ h
        launch_gemm(f0i, d0b, net1, nullptr, 128, 256, 256, 0);
        // d1 = a1 @ net1; h1 = leaky(net1, d1) in place
        launch_gemm(a1i, net1, d1b, nullptr, 128, 128, 128, 0);
        leaky_kernel<<<dim3(128 * 4, B_), 256>>>(net1, pooled, d1b, 128, 128);
        // out = sc[:, :Cx] @ x (+ biasS); out += f1 @ h1
        launch_gemm(sci, x, outn, biasSp, 128, Cx, 256, 0);
        launch_gemm(f1i, d1b, outn, nullptr, 128, 128, 128, 1);
        // pooled = vn_max_pool(out, pool_Wd[i]) over N
        launch_gemm(poolWd + i * 16384, outn, d1b, nullptr, 128, 128, 128, 0);
        pool_reduce<<<dim3(128, B_), 256>>>(outn, d1b, pooled);
        x = outn;
    }
    head_kernel<<<B_, 128>>>(pooled, actc, fcc, out);
}

// round 12
// speedup vs baseline: 1.1661x; 1.0727x over previous
#include <cuda_runtime.h>
#include <cstdint>

#define B_ 4
#define N_ 4096
#define K_ 20
#define M_ 12288  // 3*N_

// ---------------- scratch (device globals; no runtime allocation) ----------------
__device__ float g_pool64[B_ * 64 * 3 * N_];
__device__ float g_act256[B_ * 256 * 3 * N_];
__device__ float g_d0[B_ * 256 * 3 * N_];
__device__ float g_net1[B_ * 128 * 3 * N_];
__device__ float g_d1[B_ * 128 * 3 * N_];
__device__ float g_netA[B_ * 128 * 3 * N_];
__device__ float g_netB[B_ * 128 * 3 * N_];
__device__ float g_pooled[B_ * 128 * 3];
__device__ float g_biasA[B_ * 256 * 3];
__device__ float g_biasS[B_ * 128 * 3];
__device__ int   g_knn[B_ * N_ * K_];

__device__ __forceinline__ uint32_t cvt_tf32(float x) {
    uint32_t r;
    asm("cvt.rna.tf32.f32 %0, %1;" : "=r"(r) : "f"(x));
    return r;
}

// ---------------- KNN: brute-force top-20 by neg squared distance ----------------
__global__ void __launch_bounds__(128) knn_kernel(const float* __restrict__ pc,
                                                  int* __restrict__ knn) {
    __shared__ float s_pts[N_ * 3];  // 48KB
    int b = blockIdx.y;
    int tid = threadIdx.x;
    const float* pb = pc + (size_t)b * N_ * 3;
    for (int i = tid; i < N_ * 3; i += 128) s_pts[i] = pb[i];
    __syncthreads();

    int n = blockIdx.x * 128 + tid;
    float qx = s_pts[n * 3 + 0], qy = s_pts[n * 3 + 1], qz = s_pts[n * 3 + 2];
    float sqn = qx * qx + qy * qy + qz * qz;

    float best[K_];
    int bidx[K_];
#pragma unroll
    for (int i = 0; i < K_; i++) { best[i] = -1e30f; bidx[i] = 0; }
    float kmin = -1e30f;

    for (int m = 0; m < N_; m++) {
        float mx = s_pts[m * 3 + 0], my = s_pts[m * 3 + 1], mz = s_pts[m * 3 + 2];
        float inner = qx * mx + qy * my + qz * mz;
        float sqm = mx * mx + my * my + mz * mz;
        float v = 2.0f * inner - sqn - sqm;
        if (v > kmin) {  // strict: ties keep earlier index (matches lax.top_k)
            int j = K_ - 1;
            while (j > 0 && best[j - 1] < v) {
                best[j] = best[j - 1]; bidx[j] = bidx[j - 1]; j--;
            }
            best[j] = v; bidx[j] = m;
            kmin = best[K_ - 1];
        }
    }
    int* o = knn + ((size_t)b * N_ + n) * K_;
#pragma unroll
    for (int i = 0; i < K_; i++) o[i] = bidx[i];
}

// ---------------- edge conv (3->64) + vn_leaky + max-pool over k ----------------
__global__ void __launch_bounds__(128) edge_conv_kernel(
    const float* __restrict__ pc, const int* __restrict__ knn,
    const float* __restrict__ Wf, const float* __restrict__ Wd,
    const float* __restrict__ W2, float* __restrict__ outp) {
    __shared__ float s_net[64 * 60];   // [o][kk][v]
    __shared__ float s_W2T[64 * 65];   // transposed, padded: [c][o]
    __shared__ float s_dot[64 * 20];
    __shared__ float s_e[K_][3], s_cr[K_][3], s_x[3];
    __shared__ float s_Wf[192], s_Wd[192];

    int n = blockIdx.x, b = blockIdx.y;
    int tid = threadIdx.x;  // 128

    for (int i = tid; i < 192; i += 128) { s_Wf[i] = Wf[i]; s_Wd[i] = Wd[i]; }
    for (int i = tid; i < 4096; i += 128) {
        int o = i >> 6, c = i & 63;
        s_W2T[c * 65 + o] = W2[i];
    }
    if (tid < 3) s_x[tid] = pc[((size_t)b * N_ + n) * 3 + tid];
    __syncthreads();

    if (tid < K_) {
        int m = knn[((size_t)b * N_ + n) * K_ + tid];
        const float* pm = pc + ((size_t)b * N_ + m) * 3;
        float nx = pm[0], ny = pm[1], nz = pm[2];
        float x0 = s_x[0], x1 = s_x[1], x2 = s_x[2];
        s_e[tid][0] = nx - x0; s_e[tid][1] = ny - x1; s_e[tid][2] = nz - x2;
        s_cr[tid][0] = ny * x2 - nz * x1;  // cross(nbr, x)
        s_cr[tid][1] = nz * x0 - nx * x2;
        s_cr[tid][2] = nx * x1 - ny * x0;
    }
    __syncthreads();

    for (int t = tid; t < 64 * K_; t += 128) {
        int o = t / K_, kk = t % K_;
        float wf0 = s_Wf[o * 3 + 0], wf1 = s_Wf[o * 3 + 1], wf2 = s_Wf[o * 3 + 2];
        float wd0 = s_Wd[o * 3 + 0], wd1 = s_Wd[o * 3 + 1], wd2 = s_Wd[o * 3 + 2];
        float F[3], D[3];
#pragma unroll
        for (int v = 0; v < 3; v++) {
            float e = s_e[kk][v], xx = s_x[v], cr = s_cr[kk][v];
            F[v] = wf0 * e + wf1 * xx + wf2 * cr;
            D[v] = wd0 * e + wd1 * xx + wd2 * cr;
        }
        float dot = F[0] * D[0] + F[1] * D[1] + F[2] * D[2];
        if (dot < 0.0f) {
            float s = dot / (D[0] * D[0] + D[1] * D[1] + D[2] * D[2] + 1e-6f);
            F[0] -= s * D[0]; F[1] -= s * D[1]; F[2] -= s * D[2];
        }
        s_net[o * 60 + kk * 3 + 0] = F[0];
        s_net[o * 60 + kk * 3 + 1] = F[1];
        s_net[o * 60 + kk * 3 + 2] = F[2];
    }
    __syncthreads();

    {
        int og = tid >> 2;
        int kg = tid & 3;
        float acc[2][5][3] = {};
        for (int c = 0; c < 64; c++) {
            float w0 = s_W2T[c * 65 + og * 2 + 0];
            float w1 = s_W2T[c * 65 + og * 2 + 1];
#pragma unroll
            for (int q = 0; q < 5; q++) {
                int kk = kg * 5 + q;
                float n0 = s_net[c * 60 + kk * 3 + 0];
                float n1 = s_net[c * 60 + kk * 3 + 1];
                float n2 = s_net[c * 60 + kk * 3 + 2];
                acc[0][q][0] += w0 * n0; acc[0][q][1] += w0 * n1; acc[0][q][2] += w0 * n2;
                acc[1][q][0] += w1 * n0; acc[1][q][1] += w1 * n1; acc[1][q][2] += w1 * n2;
            }
        }
#pragma unroll
        for (int r = 0; r < 2; r++)
#pragma unroll
            for (int q = 0; q < 5; q++) {
                int o = og * 2 + r, kk = kg * 5 + q;
                s_dot[o * 20 + kk] =
                    s_net[o * 60 + kk * 3 + 0] * acc[r][q][0] +
                    s_net[o * 60 + kk * 3 + 1] * acc[r][q][1] +
                    s_net[o * 60 + kk * 3 + 2] * acc[r][q][2];
            }
    }
    __syncthreads();

    if (tid < 64) {
        int o = tid;
        int bk = 0; float bv = s_dot[o * 20];
#pragma unroll
        for (int kk = 1; kk < K_; kk++) {
            float v = s_dot[o * 20 + kk];
            if (v > bv) { bv = v; bk = kk; }
        }
#pragma unroll
        for (int v = 0; v < 3; v++)
            outp[(((size_t)b * 64 + o) * 3 + v) * N_ + n] = s_net[o * 60 + bk * 3 + v];
    }
}

// ---------------- 3xTF32 mma.sync batched GEMM (hybrid, single-barrier pipeline) -
// Y[b] (Co x 12288) (+)= W (Co x Ci, row stride ldw) @ X[b] (Ci x 12288) (+ bias)
#define SWH_OFF 0                         // [2][128][20]
#define SWL_OFF (2 * 128 * 20)            // [2][128][20]
#define SX_OFF  (SWL_OFF + 2 * 128 * 20)  // [2][16][136]
#define GEMM_SMEM ((SX_OFF + 2 * 16 * 136) * 4)

__global__ void __launch_bounds__(256, 2) gemm_mma(
    const float* __restrict__ W, const float* __restrict__ X,
    float* __restrict__ Y, const float* __restrict__ bias,
    int Co, int Ci, int ldw, int accflag) {
    extern __shared__ float smem[];
    float* sWh = smem + SWH_OFF;
    float* sWl = smem + SWL_OFF;
    float* sX  = smem + SX_OFF;

    int tid = threadIdx.x;
    int wid = tid >> 5, lane = tid & 31;
    int g = lane >> 2, tig = lane & 3;
    int warpM = wid & 1;    // 0..1 -> 64 rows each
    int warpN = wid >> 1;   // 0..3 -> 32 cols each
    int b = blockIdx.z;
    int m0 = blockIdx.x * 128;
    int o0 = blockIdx.y * 128;
    const float* Xb = X + (size_t)b * Ci * M_;
    float* Yb = Y + (size_t)b * Co * M_;

    int aw_o[2], aw_k[2], bx_k[2], bx_m[2];
#pragma unroll
    for (int r = 0; r < 2; r++) {
        int i = r * 256 + tid;
        aw_o[r] = i >> 2;
        aw_k[r] = (i & 3) * 4;
        bx_k[r] = i >> 5;
        bx_m[r] = (i & 31) * 4;
    }

    float c[4][4][4];
#pragma unroll
    for (int i = 0; i < 4; i++)
#pragma unroll
        for (int j = 0; j < 4; j++)
#pragma unroll
            for (int q = 0; q < 4; q++) c[i][j][q] = 0.0f;

    float4 aw[2];

#define LDG_W(kt)                                                                 \
    {                                                                             \
        _Pragma("unroll")                                                         \
        for (int r = 0; r < 2; r++)                                               \
            aw[r] = *reinterpret_cast<const float4*>(                             \
                &W[(size_t)(o0 + aw_o[r]) * ldw + (kt) + aw_k[r]]);               \
    }

#define CP_X(kt, s)                                                               \
    {                                                                             \
        _Pragma("unroll")                                                         \
        for (int r = 0; r < 2; r++) {                                             \
            unsigned int dst = (unsigned int)__cvta_generic_to_shared(            \
                &sX[((s) * 16 + bx_k[r]) * 136 + bx_m[r]]);                       \
            const float* src = &Xb[(size_t)((kt) + bx_k[r]) * M_ + m0 + bx_m[r]]; \
            asm volatile("cp.async.ca.shared.global [%0], [%1], 16;" ::           \
                         "r"(dst), "l"(src));                                     \
        }                                                                         \
        asm volatile("cp.async.commit_group;");                                   \
    }

#define CVT_STS_W(s)                                                              \
    {                                                                             \
        _Pragma("unroll")                                                         \
        for (int r = 0; r < 2; r++) {                                             \
            float4 h, l;                                                          \
            h.x = __uint_as_float(cvt_tf32(aw[r].x)); l.x = __uint_as_float(cvt_tf32(aw[r].x - h.x)); \
            h.y = __uint_as_float(cvt_tf32(aw[r].y)); l.y = __uint_as_float(cvt_tf32(aw[r].y - h.y)); \
            h.z = __uint_as_float(cvt_tf32(aw[r].z)); l.z = __uint_as_float(cvt_tf32(aw[r].z - h.z)); \
            h.w = __uint_as_float(cvt_tf32(aw[r].w)); l.w = __uint_as_float(cvt_tf32(aw[r].w - h.w)); \
            int off = ((s) * 128 + aw_o[r]) * 20 + aw_k[r];                       \
            *reinterpret_cast<float4*>(&sWh[off]) = h;                            \
            *reinterpret_cast<float4*>(&sWl[off]) = l;                            \
        }                                                                         \
    }

    int nk = Ci >> 4;
    LDG_W(0)
    CP_X(0, 0)
    CVT_STS_W(0)
    asm volatile("cp.async.wait_group 0;");
    __syncthreads();

    for (int t = 0; t < nk; t++) {
        int s = t & 1;
        if (t + 1 < nk) {
            LDG_W((t + 1) << 4)
            CP_X((t + 1) << 4, s ^ 1)  // safe: stage s^1 reads finished before prior barrier
        }

#pragma unroll
        for (int ks = 0; ks < 2; ks++) {
            int k8 = ks * 8;
            uint32_t ah[4][4];
#pragma unroll
            for (int mt = 0; mt < 4; mt++) {
                int r0 = (s * 128 + warpM * 64 + mt * 16 + g) * 20;
                int r1 = r0 + 8 * 20;
                ah[mt][0] = __float_as_uint(sWh[r0 + k8 + tig]);
                ah[mt][1] = __float_as_uint(sWh[r1 + k8 + tig]);
                ah[mt][2] = __float_as_uint(sWh[r0 + k8 + tig + 4]);
                ah[mt][3] = __float_as_uint(sWh[r1 + k8 + tig + 4]);
            }
            uint32_t bh[4][2], bl[4][2];
#pragma unroll
            for (int nt = 0; nt < 4; nt++) {
                int col = warpN * 32 + nt * 8 + g;
                float v0 = sX[(s * 16 + k8 + tig) * 136 + col];
                float v1 = sX[(s * 16 + k8 + tig + 4) * 136 + col];
                bh[nt][0] = cvt_tf32(v0); bl[nt][0] = cvt_tf32(v0 - __uint_as_float(bh[nt][0]));
                bh[nt][1] = cvt_tf32(v1); bl[nt][1] = cvt_tf32(v1 - __uint_as_float(bh[nt][1]));
            }
#define MMA(A, Bv, mt, nt)                                                        \
    asm volatile(                                                                 \
        "mma.sync.aligned.m16n8k8.row.col.f32.tf32.tf32.f32 "                     \
        "{%0,%1,%2,%3}, {%4,%5,%6,%7}, {%8,%9}, {%0,%1,%2,%3};"                   \
        : "+f"(c[mt][nt][0]), "+f"(c[mt][nt][1]),                                 \
          "+f"(c[mt][nt][2]), "+f"(c[mt][nt][3])                                  \
        : "r"(A[mt][0]), "r"(A[mt][1]), "r"(A[mt][2]), "r"(A[mt][3]),             \
          "r"(Bv[nt][0]), "r"(Bv[nt][1]))
#pragma unroll
            for (int mt = 0; mt < 4; mt++)
#pragma unroll
                for (int nt = 0; nt < 4; nt++) {
                    MMA(ah, bh, mt, nt);
                    MMA(ah, bl, mt, nt);
                }
            uint32_t al[4][4];
#pragma unroll
            for (int mt = 0; mt < 4; mt++) {
                int r0 = (s * 128 + warpM * 64 + mt * 16 + g) * 20;
                int r1 = r0 + 8 * 20;
                al[mt][0] = __float_as_uint(sWl[r0 + k8 + tig]);
                al[mt][1] = __float_as_uint(sWl[r1 + k8 + tig]);
                al[mt][2] = __float_as_uint(sWl[r0 + k8 + tig + 4]);
                al[mt][3] = __float_as_uint(sWl[r1 + k8 + tig + 4]);
            }
#pragma unroll
            for (int mt = 0; mt < 4; mt++)
#pragma unroll
                for (int nt = 0; nt < 4; nt++) MMA(al, bh, mt, nt);
#undef MMA
        }
        if (t + 1 < nk) {
            CVT_STS_W(s ^ 1)   // safe: stage s^1 reads finished before prior barrier
            asm volatile("cp.async.wait_group 0;");
            __syncthreads();   // single barrier per tile
        }
    }
#undef LDG_W
#undef CP_X
#undef CVT_STS_W

    int v = m0 >> 12;
#pragma unroll
    for (int mt = 0; mt < 4; mt++) {
        int o = o0 + warpM * 64 + mt * 16 + g;
        float bv0 = bias ? bias[((size_t)b * Co + o) * 3 + v] : 0.0f;
        float bv1 = bias ? bias[((size_t)b * Co + o + 8) * 3 + v] : 0.0f;
#pragma unroll
        for (int nt = 0; nt < 4; nt++) {
            size_t col = m0 + warpN * 32 + nt * 8 + 2 * tig;
            float2* p0 = reinterpret_cast<float2*>(&Yb[(size_t)o * M_ + col]);
            float2* p1 = reinterpret_cast<float2*>(&Yb[(size_t)(o + 8) * M_ + col]);
            float2 v0 = make_float2(c[mt][nt][0] + bv0, c[mt][nt][1] + bv0);
            float2 v1 = make_float2(c[mt][nt][2] + bv1, c[mt][nt][3] + bv1);
            if (accflag) {
                float2 o0v = *p0, o1v = *p1;
                v0.x += o0v.x; v0.y += o0v.y; v1.x += o1v.x; v1.y += o1v.y;
            }
            *p0 = v0;
            *p1 = v1;
        }
    }
}

// ---------------- vn_leaky (float4): h = leaky(x, d) IN PLACE into d -------------
__global__ void __launch_bounds__(256) leaky_kernel(
    const float* __restrict__ x, const float* __restrict__ pooled,
    float* __restrict__ d, int C, int Cx) {
    int b = blockIdx.y;
    int e = blockIdx.x * 256 + threadIdx.x;  // over C*N/4
    int n = (e & 1023) * 4;
    int c = e >> 10;
    float4 x0, x1, x2;
    if (c < Cx) {
        size_t base = ((size_t)(b * Cx + c) * 3) * N_ + n;
        x0 = *reinterpret_cast<const float4*>(&x[base]);
        x1 = *reinterpret_cast<const float4*>(&x[base + N_]);
        x2 = *reinterpret_cast<const float4*>(&x[base + 2 * N_]);
    } else {
        const float* p = pooled + (size_t)(b * 128 + (c - Cx)) * 3;
        x0 = make_float4(p[0], p[0], p[0], p[0]);
        x1 = make_float4(p[1], p[1], p[1], p[1]);
        x2 = make_float4(p[2], p[2], p[2], p[2]);
    }
    size_t db = ((size_t)(b * C + c) * 3) * N_ + n;
    float4 d0 = *reinterpret_cast<float4*>(&d[db]);
    float4 d1 = *reinterpret_cast<float4*>(&d[db + N_]);
    float4 d2 = *reinterpret_cast<float4*>(&d[db + 2 * N_]);
#define LEAKY1(X0, X1, X2, D0, D1, D2)                                   \
    {                                                                    \
        float dot = X0 * D0 + X1 * D1 + X2 * D2;                         \
        if (dot < 0.0f) {                                                \
            float s = dot / (D0 * D0 + D1 * D1 + D2 * D2 + 1e-6f);       \
            X0 -= s * D0; X1 -= s * D1; X2 -= s * D2;                    \
        }                                                                \
        D0 = X0; D1 = X1; D2 = X2;                                       \
    }
    LEAKY1(x0.x, x1.x, x2.x, d0.x, d1.x, d2.x)
    LEAKY1(x0.y, x1.y, x2.y, d0.y, d1.y, d2.y)
    LEAKY1(x0.z, x1.z, x2.z, d0.z, d1.z, d2.z)
    LEAKY1(x0.w, x1.w, x2.w, d0.w, d1.w, d2.w)
#undef LEAKY1
    *reinterpret_cast<float4*>(&d[db]) = d0;
    *reinterpret_cast<float4*>(&d[db + N_]) = d1;
    *reinterpret_cast<float4*>(&d[db + 2 * N_]) = d2;
}

// ---------------- vn_max_pool over N: argmax of <net,d>, gather ------------------
__global__ void __launch_bounds__(256) pool_reduce(
    const float* __restrict__ net, const float* __restrict__ d,
    float* __restrict__ pooled) {
    __shared__ float sv[256];
    __shared__ int si[256];
    int c = blockIdx.x, b = blockIdx.y, tid = threadIdx.x;
    size_t base = ((size_t)(b * 128 + c) * 3) * N_;
    float bv = -3.4e38f; int bi = 0;
    for (int n = tid; n < N_; n += 256) {
        float dot = net[base + n] * d[base + n]
                  + net[base + N_ + n] * d[base + N_ + n]
                  + net[base + 2 * N_ + n] * d[base + 2 * N_ + n];
        if (dot > bv) { bv = dot; bi = n; }
    }
    sv[tid] = bv; si[tid] = bi;
    __syncthreads();
    for (int s = 128; s > 0; s >>= 1) {
        if (tid < s) {
            float v2 = sv[tid + s]; int i2 = si[tid + s];
            if (v2 > sv[tid] || (v2 == sv[tid] && i2 < si[tid])) {
                sv[tid] = v2; si[tid] = i2;  // first-index-wins = jnp.argmax
            }
        }
        __syncthreads();
    }
    if (tid < 3) pooled[(size_t)(b * 128 + c) * 3 + tid] = net[base + (size_t)tid * N_ + si[0]];
}

// ---------------- bias from broadcast-concat: bias[b,o,v] = W[o,128:] . pooled ---
__global__ void bias_kernel(const float* __restrict__ W, const float* __restrict__ pooled,
                            float* __restrict__ bias, int Co) {
    __shared__ float sp[128];
    int b = blockIdx.x, v = blockIdx.y, o = threadIdx.x;
    if (o < 128) sp[o] = pooled[(size_t)(b * 128 + o) * 3 + v];
    __syncthreads();
    const float* w = W + (size_t)o * 256 + 128;
    float acc = 0.0f;
#pragma unroll 8
    for (int c = 0; c < 128; c++) acc += w[c] * sp[c];
    bias[((size_t)b * Co + o) * 3 + v] = acc;
}

// ---------------- final head: c = fcc @ leaky(nt, actc @ nt) ---------------------
__global__ void __launch_bounds__(128) head_kernel(
    const float* __restrict__ pooled, const float* __restrict__ Wa,
    const float* __restrict__ Wc, float* __restrict__ out) {
    __shared__ float s_nt[384], s_h[384];
    int b = blockIdx.x, o = threadIdx.x;
    for (int i = o; i < 384; i += 128) s_nt[i] = pooled[b * 384 + i];
    __syncthreads();
    float d0 = 0, d1 = 0, d2 = 0;
    for (int c = 0; c < 128; c++) {
        float w = Wa[o * 128 + c];
        d0 += w * s_nt[c * 3]; d1 += w * s_nt[c * 3 + 1]; d2 += w * s_nt[c * 3 + 2];
    }
    float x0 = s_nt[o * 3], x1 = s_nt[o * 3 + 1], x2 = s_nt[o * 3 + 2];
    float dot = x0 * d0 + x1 * d1 + x2 * d2;
    if (dot < 0.0f) {
        float s = dot / (d0 * d0 + d1 * d1 + d2 * d2 + 1e-6f);
        x0 -= s * d0; x1 -= s * d1; x2 -= s * d2;
    }
    s_h[o * 3] = x0; s_h[o * 3 + 1] = x1; s_h[o * 3 + 2] = x2;
    __syncthreads();
    if (o < 64) {
        float a0 = 0, a1 = 0, a2 = 0;
        for (int c = 0; c < 128; c++) {
            float w = Wc[o * 128 + c];
            a0 += w * s_h[c * 3]; a1 += w * s_h[c * 3 + 1]; a2 += w * s_h[c * 3 + 2];
        }
        out[b * 192 + o * 3 + 0] = a0;
        out[b * 192 + o * 3 + 1] = a1;
        out[b * 192 + o * 3 + 2] = a2;
    }
}

static void launch_gemm(const float* W, const float* X, float* Y, const float* bias,
                        int Co, int Ci, int ldw, int accflag, cudaStream_t st) {
    gemm_mma<<<dim3(96, Co / 128, B_), 256, GEMM_SMEM, st>>>(W, X, Y, bias, Co, Ci, ldw, accflag);
}

extern "C" void kernel_launch(void* const* d_in, const int* in_sizes, int n_in,
                              void* d_out, int out_size) {
    const float* pc      = (const float*)d_in[0];
    const float* conv_Wf = (const float*)d_in[1];
    const float* conv_Wd = (const float*)d_in[2];
    const float* pp_Wd   = (const float*)d_in[3];
    const float* fc_pos  = (const float*)d_in[4];
    const float* a0      = (const float*)d_in[5];
    const float* f0      = (const float*)d_in[6];
    const float* a1      = (const float*)d_in[7];
    const float* f1      = (const float*)d_in[8];
    const float* sc      = (const float*)d_in[9];
    const float* poolWd  = (const float*)d_in[10];
    const float* actc    = (const float*)d_in[11];
    const float* fcc     = (const float*)d_in[12];
    float* out = (float*)d_out;

    cudaFuncSetAttribute(gemm_mma, cudaFuncAttributeMaxDynamicSharedMemorySize, GEMM_SMEM);

    float *pool64, *act256, *d0b, *net1, *d1b, *netA, *netB, *pooled, *biasA, *biasS;
    int* knn;
    cudaGetSymbolAddress((void**)&pool64, g_pool64);
    cudaGetSymbolAddress((void**)&act256, g_act256);
    cudaGetSymbolAddress((void**)&d0b,    g_d0);
    cudaGetSymbolAddress((void**)&net1,   g_net1);
    cudaGetSymbolAddress((void**)&d1b,    g_d1);
    cudaGetSymbolAddress((void**)&netA,   g_netA);
    cudaGetSymbolAddress((void**)&netB,   g_netB);
    cudaGetSymbolAddress((void**)&pooled, g_pooled);
    cudaGetSymbolAddress((void**)&biasA,  g_biasA);
    cudaGetSymbolAddress((void**)&biasS,  g_biasS);
    cudaGetSymbolAddress((void**)&knn,    g_knn);

    // side stream for the independent shortcut-GEMM chain (created & leaked:
    // kernel_launch runs only twice — correctness + capture — replays don't call it)
    cudaStream_t s1;
    cudaStreamCreateWithFlags(&s1, cudaStreamNonBlocking);

    knn_kernel<<<dim3(N_ / 128, B_), 128>>>(pc, knn);
    edge_conv_kernel<<<dim3(N_, B_), 128>>>(pc, knn, conv_Wf, conv_Wd, pp_Wd, pool64);
    // fc_pos: [256,64] @ [64, 12288]
    launch_gemm(fc_pos, pool64, act256, nullptr, 256, 64, 64, 0, 0);

    float* nets[2] = {netA, netB};
    const float* x = act256;
    for (int i = 0; i < 5; i++) {
        const float* a0i = a0 + i * 65536;
        const float* f0i = f0 + i * 32768;
        const float* a1i = a1 + i * 16384;
        const float* f1i = f1 + i * 16384;
        const float* sci = sc + i * 32768;
        float* outn = nets[i & 1];
        int Cx = (i == 0) ? 256 : 128;
        const float* biasAp = (i == 0) ? nullptr : biasA;
        const float* biasSp = (i == 0) ? nullptr : biasS;

        // fork: s1 picks up after main's latest (x and pooled are ready)
        cudaEvent_t evF, evS;
        cudaEventCreateWithFlags(&evF, cudaEventDisableTiming);
        cudaEventCreateWithFlags(&evS, cudaEventDisableTiming);
        cudaEventRecord(evF, 0);
        cudaStreamWaitEvent(s1, evF, 0);
        // s1: shortcut chain  out = sc[:, :Cx] @ x (+ biasS)
        if (i > 0) bias_kernel<<<dim3(B_, 3), 128, 0, s1>>>(sci, pooled, biasS, 128);
        launch_gemm(sci, x, outn, biasSp, 128, Cx, 256, 0, s1);
        cudaEventRecord(evS, s1);

        // main: activation chain
        if (i > 0) bias_kernel<<<dim3(B_, 3), 256>>>(a0i, pooled, biasA, 256);
        // d0 = a0[:, :Cx] @ x (+ biasA)
        launch_gemm(a0i, x, d0b, biasAp, 256, Cx, 256, 0, 0);
        // h = leaky(concat(x,pooled), d0) in place (256 ch)
        leaky_kernel<<<dim3(256 * 4, B_), 256>>>(x, pooled, d0b, 256, Cx);
        // net1 = f0 @ h
        launch_gemm(f0i, d0b, net1, nullptr, 128, 256, 256, 0, 0);
        // d1 = a1 @ net1; h1 = leaky(net1, d1) in place
        launch_gemm(a1i, net1, d1b, nullptr, 128, 128, 128, 0, 0);
        leaky_kernel<<<dim3(128 * 4, B_), 256>>>(net1, pooled, d1b, 128, 128);

        // join: f1 accumulates into sc's output
        cudaStreamWaitEvent(0, evS, 0);
        launch_gemm(f1i, d1b, outn, nullptr, 128, 128, 128, 1, 0);
        // pooled = vn_max_pool(out, pool_Wd[i]) over N
        launch_gemm(poolWd + i * 16384, outn, d1b, nullptr, 128, 128, 128, 0, 0);
        pool_reduce<<<dim3(128, B_), 256>>>(outn, d1b, pooled);
        x = outn;
    }
    head_kernel<<<B_, 128>>>(pooled, actc, fcc, out);
}